// round 15
// baseline (speedup 1.0000x reference)
#include <cuda_runtime.h>
#include <cuda_fp16.h>
#include <cstdint>

#define NMAX 100000
#define EMAX 1600000
#define FULLMASK 0xffffffffu

// ---------------- scratch (static device allocations; no cudaMalloc) -------
__device__ __half g_h0[NMAX * 128];
__device__ __half g_hA[2 * NMAX * 128];
__device__ __half g_hB[2 * NMAX * 128];
__device__ __half g_out[2 * NMAX * 128];
__device__ __half g_agg[2 * NMAX * 128];
__device__ __half g_pw[7 * 128 * 256];      // packed fp16 weights [g][nn][k]
__device__ int    g_counts[2 * NMAX];
__device__ int    g_rowptr[2 * NMAX + 1];
__device__ int    g_cursor[2 * NMAX];
__device__ int    g_srcs[2 * EMAX];
__device__ int    g_bsums[256];

// mma.sync m16n8k16 f16 -> f32 accum (portable, sm_80+)
__device__ __forceinline__ void mma_f16(float* d, const uint32_t* a, const uint32_t* b) {
    asm volatile(
        "mma.sync.aligned.m16n8k16.row.col.f32.f16.f16.f32 "
        "{%0,%1,%2,%3}, {%4,%5,%6,%7}, {%8,%9}, {%0,%1,%2,%3};"
        : "+f"(d[0]), "+f"(d[1]), "+f"(d[2]), "+f"(d[3])
        : "r"(a[0]), "r"(a[1]), "r"(a[2]), "r"(a[3]), "r"(b[0]), "r"(b[1]));
}

// smem geometry (halves): A[128][264] | B[128][264] | bias[128]f32
static constexpr int LDAH   = 264;
static constexpr int SMEM_GEMM = (2 * 128 * LDAH) * 2 + 128 * 4;   // 136192 B

// ---------------- weight pre-pack: fp32 [k][nn] -> fp16 [g][nn][k] ----------
__global__ void k_pack(const float* __restrict__ Wl, const float* __restrict__ Wr,
                       const float* __restrict__ w_emb, __half* __restrict__ pw)
{
    __shared__ float tile[32][33];
    const int g = blockIdx.z, k0 = blockIdx.x * 32, n0 = blockIdx.y * 32;
    const int tx = threadIdx.x, ty = threadIdx.y;
    #pragma unroll
    for (int i = 0; i < 4; ++i) {
        int k = k0 + ty + 8 * i, nn = n0 + tx;
        float v;
        if (g < 6) v = (k < 128) ? Wl[((size_t)g * 128 + k) * 128 + nn]
                                 : Wr[((size_t)g * 128 + (k - 128)) * 128 + nn];
        else       v = (k < 128) ? w_emb[(size_t)k * 128 + nn] : 0.f;
        tile[ty + 8 * i][tx] = v;
    }
    __syncthreads();
    #pragma unroll
    for (int i = 0; i < 4; ++i) {
        int k = k0 + tx, nn = n0 + ty + 8 * i;
        pw[((size_t)g * 128 + nn) * 256 + k] = __float2half_rn(tile[tx][ty + 8 * i]);
    }
}

// ---------------- dual-chain mean-aggregation gather -------------------------
// Warp per global node (2n). 16 warps/CTA. Software-pipelined: next batch's
// srcs indices are prefetched before consuming current rows. aggm written
// evict-first (.cs) to preserve hin residency in L2 (validated R14).
__global__ __launch_bounds__(512) void k_gather(
    const __half* __restrict__ hin0, const __half* __restrict__ hin1,
    const int* __restrict__ srcs, const int* __restrict__ rowptr,
    __half* __restrict__ aggm, int n)
{
    const int lane = threadIdx.x & 31;
    const int node_g = blockIdx.x * 16 + (threadIdx.x >> 5);
    if (node_g >= 2 * n) return;
    const uint2* hb = (const uint2*)((node_g >= n) ? hin1 : hin0);  // row = 32 uint2
    const int beg = __ldg(&rowptr[node_g]);
    const int end = __ldg(&rowptr[node_g + 1]);
    float a0 = 0.f, a1 = 0.f, a2 = 0.f, a3 = 0.f;
    int e = beg;
    if (e + 16 <= end) {
        int s[16];
        #pragma unroll
        for (int j = 0; j < 16; ++j) s[j] = __ldg(&srcs[e + j]);
        #pragma unroll 1
        while (true) {
            uint2 u[16];
            #pragma unroll
            for (int j = 0; j < 16; ++j) u[j] = __ldg(hb + (size_t)s[j] * 32 + lane);
            const int e_next = e + 16;
            const bool more = (e_next + 16 <= end);
            if (more) {                       // prefetch next indices early
                #pragma unroll
                for (int j = 0; j < 16; ++j) s[j] = __ldg(&srcs[e_next + j]);
            }
            #pragma unroll
            for (int j = 0; j < 16; ++j) {
                float2 f0 = __half22float2(*(const __half2*)&u[j].x);
                float2 f1 = __half22float2(*(const __half2*)&u[j].y);
                a0 += f0.x; a1 += f0.y; a2 += f1.x; a3 += f1.y;
            }
            e = e_next;
            if (!more) break;
        }
    }
    #pragma unroll 1
    for (; e + 4 <= end; e += 4) {
        int s[4];
        #pragma unroll
        for (int j = 0; j < 4; ++j) s[j] = __ldg(&srcs[e + j]);
        uint2 u[4];
        #pragma unroll
        for (int j = 0; j < 4; ++j) u[j] = __ldg(hb + (size_t)s[j] * 32 + lane);
        #pragma unroll
        for (int j = 0; j < 4; ++j) {
            float2 f0 = __half22float2(*(const __half2*)&u[j].x);
            float2 f1 = __half22float2(*(const __half2*)&u[j].y);
            a0 += f0.x; a1 += f0.y; a2 += f1.x; a3 += f1.y;
        }
    }
    #pragma unroll 1
    for (; e < end; ++e) {
        uint2 u = __ldg(hb + (size_t)__ldg(&srcs[e]) * 32 + lane);
        float2 f0 = __half22float2(*(const __half2*)&u.x);
        float2 f1 = __half22float2(*(const __half2*)&u.y);
        a0 += f0.x; a1 += f0.y; a2 += f1.x; a3 += f1.y;
    }
    const float inv = 1.0f / fmaxf((float)(end - beg), 1.0f);
    int2 out;
    __half2 o01 = __floats2half2_rn(a0 * inv, a1 * inv);
    __half2 o23 = __floats2half2_rn(a2 * inv, a3 * inv);
    out.x = *(const int*)&o01;
    out.y = *(const int*)&o23;
    __stcs((int2*)((uint2*)(aggm + (size_t)node_g * 128) + lane), out);
}

// ---------------- dual-chain fused K=256 GEMM layer (fp16 MMA) ---------------
// Grid = tiles (embed, chain0 only) or 2*tiles (dual). Per CTA: 128-node tile.
// out = relu([aggm|h] @ pwg^T + bias).  do_agg=0 -> embedding (fp32 input).
__global__ __launch_bounds__(512, 1) void k_sage_gemm(
    const __half* __restrict__ aggm,
    const void* __restrict__ h0v, const void* __restrict__ h1v,
    const __half* __restrict__ pw0, const __half* __restrict__ pw1,
    const float* __restrict__ b0, const float* __restrict__ b1,
    __half* __restrict__ out0, __half* __restrict__ out1,
    int n, int tiles, int do_agg)
{
    extern __shared__ __align__(16) char smem_raw[];
    __half* sA = (__half*)smem_raw;                 // [128][264]
    __half* sB = sA + 128 * LDAH;                   // [128][264]
    float*  sBias = (float*)(sB + 128 * LDAH);      // [128]
    const int tid = threadIdx.x;
    const int wid = tid >> 5;
    const int lane = tid & 31;

    int tile = blockIdx.x, chain = 0;
    if (tile >= tiles) { chain = 1; tile -= tiles; }
    const __half* pwg  = chain ? pw1 : pw0;
    const float*  bias = chain ? b1 : b0;
    const void*   hroot_v = chain ? h1v : h0v;
    __half*       hout = chain ? out1 : out0;

    // B copy: coalesced uint4, 128 rows x 32 chunks
    {
        const uint4* pw4 = (const uint4*)pwg;
        #pragma unroll
        for (int i = tid; i < 4096; i += 512) {
            int row = i >> 5, c = i & 31;
            ((uint4*)(sB + row * LDAH))[c] = __ldg(pw4 + i);
        }
    }
    if (tid < 128) sBias[tid] = bias[tid];

    // A staging: warp owns 8 rows; batch ALL loads first (MLP~16), then store
    {
        uint2 ua[8], uh[8];
        #pragma unroll
        for (int i = 0; i < 8; ++i) {
            const int node = tile * 128 + wid * 8 + i;
            ua[i] = make_uint2(0u, 0u); uh[i] = make_uint2(0u, 0u);
            if (node < n) {
                if (do_agg) {
                    int2 t = __ldcs((const int2*)(aggm + (size_t)(chain * n + node) * 128) + lane);
                    ua[i] = make_uint2((uint32_t)t.x, (uint32_t)t.y);
                    uh[i] = __ldg((const uint2*)((const __half*)hroot_v + (size_t)node * 128) + lane);
                } else {
                    float4 v;
                    const float4* px = (const float4*)hroot_v + (size_t)node * 32 + lane;
                    v = __ldcs(px);              // x is read exactly once: evict-first
                    *(__half2*)&ua[i].x = __floats2half2_rn(v.x, v.y);
                    *(__half2*)&ua[i].y = __floats2half2_rn(v.z, v.w);
                }
            }
        }
        #pragma unroll
        for (int i = 0; i < 8; ++i) {
            const int row = wid * 8 + i;
            ((uint2*)(sA + row * LDAH))[lane] = ua[i];          // cols 0..127 (mean)
            ((uint2*)(sA + row * LDAH + 128))[lane] = uh[i];    // cols 128..255 (root)
        }
    }
    __syncthreads();

    // GEMM: warp wid -> rows (wid&3)*32.., cols (wid>>2)*32..; K=256
    const int wm = wid & 3;
    const int wn = wid >> 2;
    const int tr = lane >> 2;
    const int tc = lane & 3;
    float C[2][4][4];
    #pragma unroll
    for (int mt = 0; mt < 2; ++mt)
        #pragma unroll
        for (int nt = 0; nt < 4; ++nt)
            #pragma unroll
            for (int q = 0; q < 4; ++q) C[mt][nt][q] = 0.f;

    #pragma unroll 4
    for (int ks = 0; ks < 16; ++ks) {
        const int kb = ks * 16 + 2 * tc;
        uint32_t af[2][4], bf[4][2];
        #pragma unroll
        for (int mt = 0; mt < 2; ++mt) {
            const __half* p = sA + (wm * 32 + mt * 16 + tr) * LDAH + kb;
            af[mt][0] = *(const uint32_t*)(p);
            af[mt][1] = *(const uint32_t*)(p + 8 * LDAH);
            af[mt][2] = *(const uint32_t*)(p + 8);
            af[mt][3] = *(const uint32_t*)(p + 8 * LDAH + 8);
        }
        #pragma unroll
        for (int nt = 0; nt < 4; ++nt) {
            const __half* p = sB + (wn * 32 + nt * 8 + tr) * LDAH + kb;
            bf[nt][0] = *(const uint32_t*)(p);
            bf[nt][1] = *(const uint32_t*)(p + 8);
        }
        #pragma unroll
        for (int mt = 0; mt < 2; ++mt)
            #pragma unroll
            for (int nt = 0; nt < 4; ++nt)
                mma_f16(C[mt][nt], af[mt], bf[nt]);
    }

    // epilogue: bias + relu -> fp16
    #pragma unroll
    for (int mt = 0; mt < 2; ++mt) {
        int r0i = wm * 32 + mt * 16 + tr;
        int nd0 = tile * 128 + r0i;
        int nd1 = nd0 + 8;
        #pragma unroll
        for (int nt = 0; nt < 4; ++nt) {
            int col = wn * 32 + nt * 8 + tc * 2;
            float bb0 = sBias[col], bb1 = sBias[col + 1];
            if (nd0 < n) {
                __half2 v = __floats2half2_rn(fmaxf(C[mt][nt][0] + bb0, 0.f),
                                              fmaxf(C[mt][nt][1] + bb1, 0.f));
                *(__half2*)(hout + (size_t)nd0 * 128 + col) = v;
            }
            if (nd1 < n) {
                __half2 v = __floats2half2_rn(fmaxf(C[mt][nt][2] + bb0, 0.f),
                                              fmaxf(C[mt][nt][3] + bb1, 0.f));
                *(__half2*)(hout + (size_t)nd1 * 128 + col) = v;
            }
        }
    }
}

// ---------------- dual CSR build: count + 3-stage scan + scatter -------------
__global__ void k_count(const int* __restrict__ e0, const int* __restrict__ e1,
                        int* __restrict__ counts, int E, int n)
{
    int i = blockIdx.x * blockDim.x + threadIdx.x;
    if (i < E)          atomicAdd(&counts[__ldg(&e0[E + i])], 1);
    else if (i < 2 * E) atomicAdd(&counts[n + __ldg(&e1[E + (i - E)])], 1);
}

__global__ __launch_bounds__(1024) void k_scan1(
    const int* __restrict__ counts, int* __restrict__ rowptr,
    int* __restrict__ bsums, int n2)
{
    __shared__ int s[1024];
    int i = blockIdx.x * 1024 + threadIdx.x;
    int v = (i < n2) ? counts[i] : 0;
    s[threadIdx.x] = v;
    __syncthreads();
    #pragma unroll
    for (int off = 1; off < 1024; off <<= 1) {
        int t = (threadIdx.x >= off) ? s[threadIdx.x - off] : 0;
        __syncthreads();
        s[threadIdx.x] += t;
        __syncthreads();
    }
    if (i < n2) rowptr[i] = s[threadIdx.x] - v;
    if (threadIdx.x == 1023) bsums[blockIdx.x] = s[1023];
}

__global__ __launch_bounds__(256) void k_scan2(int* __restrict__ bsums, int nb,
                                               int* __restrict__ rowptr, int n2)
{
    __shared__ int s[256];
    int t = threadIdx.x;
    int v = (t < nb) ? bsums[t] : 0;
    s[t] = v;
    __syncthreads();
    #pragma unroll
    for (int off = 1; off < 256; off <<= 1) {
        int u = (t >= off) ? s[t - off] : 0;
        __syncthreads();
        s[t] += u;
        __syncthreads();
    }
    if (t < nb) bsums[t] = s[t] - v;            // exclusive
    if (t == nb - 1) rowptr[n2] = s[t];
}

__global__ void k_scan3(int* __restrict__ rowptr, const int* __restrict__ bsums,
                        int* __restrict__ cursor, int* __restrict__ counts, int n2)
{
    int i = blockIdx.x * 1024 + threadIdx.x;
    if (i < n2) {
        int v = rowptr[i] + bsums[blockIdx.x];
        rowptr[i] = v;
        cursor[i] = v;
        counts[i] = 0;          // restore invariant for next graph replay
    }
}

__global__ void k_scatter(const int* __restrict__ e0, const int* __restrict__ e1,
                          int* __restrict__ cursor, int* __restrict__ srcs,
                          int E, int n)
{
    int i = blockIdx.x * blockDim.x + threadIdx.x;
    if (i < E) {
        int d = __ldg(&e0[E + i]);
        int p = atomicAdd(&cursor[d], 1);
        srcs[p] = __ldg(&e0[i]);
    } else if (i < 2 * E) {
        int j = i - E;
        int d = __ldg(&e1[E + j]);
        int p = atomicAdd(&cursor[n + d], 1);
        srcs[p] = __ldg(&e1[j]);
    }
}

// ---------------- fused attention combine + classifier/pattern heads --------
__global__ __launch_bounds__(256) void k_att_heads(
    const __half* __restrict__ o0, const __half* __restrict__ o1,
    const float* __restrict__ watt, const float* __restrict__ batt,
    const float* __restrict__ wc1, const float* __restrict__ bc1,
    const float* __restrict__ wc2, const float* __restrict__ bc2,
    const float* __restrict__ wp1, const float* __restrict__ bp1,
    const float* __restrict__ wp2, const float* __restrict__ bp2,
    float4* __restrict__ agg, float* __restrict__ fraud, float* __restrict__ pat,
    int n)
{
    extern __shared__ float sm[];
    float* sC1 = sm;
    float* sP1 = sC1 + 8192;
    float* sC2 = sP1 + 8192;
    float* sP2 = sC2 + 128;
    float* sBC1 = sP2 + 320;
    float* sBP1 = sBC1 + 64;
    float* sBC2 = sBP1 + 64;
    float* sBP2 = sBC2 + 2;
    for (int i = threadIdx.x; i < 8192; i += blockDim.x) { sC1[i] = wc1[i]; sP1[i] = wp1[i]; }
    for (int i = threadIdx.x; i < 128;  i += blockDim.x) sC2[i] = wc2[i];
    for (int i = threadIdx.x; i < 320;  i += blockDim.x) sP2[i] = wp2[i];
    for (int i = threadIdx.x; i < 64;   i += blockDim.x) { sBC1[i] = bc1[i]; sBP1[i] = bp1[i]; }
    if (threadIdx.x < 2) sBC2[threadIdx.x] = bc2[threadIdx.x];
    if (threadIdx.x < 5) sBP2[threadIdx.x] = bp2[threadIdx.x];
    __syncthreads();

    const int lane = threadIdx.x & 31;
    const int gw = blockIdx.x * (blockDim.x >> 5) + (threadIdx.x >> 5);
    const int nw = gridDim.x * (blockDim.x >> 5);
    const float2* sC1v = (const float2*)sC1;
    const float2* sP1v = (const float2*)sP1;

    const int k0 = lane * 4;
    float wa0[4], wa1[4], wb0[4], wb1[4];
    #pragma unroll
    for (int c = 0; c < 4; ++c) {
        wa0[c] = __ldg(&watt[(k0 + c) * 2 + 0]);
        wa1[c] = __ldg(&watt[(k0 + c) * 2 + 1]);
        wb0[c] = __ldg(&watt[(128 + k0 + c) * 2 + 0]);
        wb1[c] = __ldg(&watt[(128 + k0 + c) * 2 + 1]);
    }
    const float bt0 = __ldg(&batt[0]), bt1 = __ldg(&batt[1]);

    const int hA = 2 * lane, hBb = 2 * lane + 1;
    const float c2a0 = sC2[hA * 2 + 0], c2a1 = sC2[hA * 2 + 1];
    const float c2b0 = sC2[hBb * 2 + 0], c2b1 = sC2[hBb * 2 + 1];
    float p2a[5], p2b[5];
    #pragma unroll
    for (int j = 0; j < 5; ++j) { p2a[j] = sP2[hA * 5 + j]; p2b[j] = sP2[hBb * 5 + j]; }
    const float bC1a = sBC1[hA], bC1b = sBC1[hBb];
    const float bP1a = sBP1[hA], bP1b = sBP1[hBb];
    const float bC2_0 = sBC2[0], bC2_1 = sBC2[1];
    float bP2v[5];
    #pragma unroll
    for (int j = 0; j < 5; ++j) bP2v[j] = sBP2[j];

    for (int node = gw; node < n; node += nw) {
        int2 ta = __ldcs((const int2*)(o0 + (size_t)node * 128) + lane);
        int2 tb = __ldcs((const int2*)(o1 + (size_t)node * 128) + lane);
        uint2 ua = make_uint2((uint32_t)ta.x, (uint32_t)ta.y);
        uint2 ub = make_uint2((uint32_t)tb.x, (uint32_t)tb.y);
        float2 a01 = __half22float2(*(const __half2*)&ua.x);
        float2 a23 = __half22float2(*(const __half2*)&ua.y);
        float2 b01 = __half22float2(*(const __half2*)&ub.x);
        float2 b23 = __half22float2(*(const __half2*)&ub.y);
        float p0 = a01.x * wa0[0] + a01.y * wa0[1] + a23.x * wa0[2] + a23.y * wa0[3]
                 + b01.x * wb0[0] + b01.y * wb0[1] + b23.x * wb0[2] + b23.y * wb0[3];
        float p1 = a01.x * wa1[0] + a01.y * wa1[1] + a23.x * wa1[2] + a23.y * wa1[3]
                 + b01.x * wb1[0] + b01.y * wb1[1] + b23.x * wb1[2] + b23.y * wb1[3];
        #pragma unroll
        for (int off = 16; off; off >>= 1) {
            p0 += __shfl_xor_sync(FULLMASK, p0, off);
            p1 += __shfl_xor_sync(FULLMASK, p1, off);
        }
        float z0 = p0 + bt0, z1 = p1 + bt1;
        float m = fmaxf(z0, z1);
        float e0 = expf(z0 - m), e1 = expf(z1 - m);
        float inv = 1.0f / (e0 + e1);
        float w0 = e0 * inv, w1 = e1 * inv;
        float4 ar;
        ar.x = w0 * a01.x + w1 * b01.x;
        ar.y = w0 * a01.y + w1 * b01.y;
        ar.z = w0 * a23.x + w1 * b23.x;
        ar.w = w0 * a23.y + w1 * b23.y;
        agg[node * 32 + lane] = ar;

        float hc0 = bC1a, hc1 = bC1b, hp0 = bP1a, hp1 = bP1b;
        #pragma unroll 4
        for (int kk = 0; kk < 32; ++kk) {
            float av[4];
            av[0] = __shfl_sync(FULLMASK, ar.x, kk);
            av[1] = __shfl_sync(FULLMASK, ar.y, kk);
            av[2] = __shfl_sync(FULLMASK, ar.z, kk);
            av[3] = __shfl_sync(FULLMASK, ar.w, kk);
            #pragma unroll
            for (int j = 0; j < 4; ++j) {
                int k = kk * 4 + j;
                float2 wc = sC1v[k * 32 + lane];
                float2 wp = sP1v[k * 32 + lane];
                hc0 += av[j] * wc.x; hc1 += av[j] * wc.y;
                hp0 += av[j] * wp.x; hp1 += av[j] * wp.y;
            }
        }
        hc0 = fmaxf(hc0, 0.f); hc1 = fmaxf(hc1, 0.f);
        hp0 = fmaxf(hp0, 0.f); hp1 = fmaxf(hp1, 0.f);

        float f0 = hc0 * c2a0 + hc1 * c2b0;
        float f1 = hc0 * c2a1 + hc1 * c2b1;
        float q[5];
        #pragma unroll
        for (int j = 0; j < 5; ++j) q[j] = hp0 * p2a[j] + hp1 * p2b[j];
        #pragma unroll
        for (int off = 16; off; off >>= 1) {
            f0 += __shfl_xor_sync(FULLMASK, f0, off);
            f1 += __shfl_xor_sync(FULLMASK, f1, off);
            #pragma unroll
            for (int j = 0; j < 5; ++j) q[j] += __shfl_xor_sync(FULLMASK, q[j], off);
        }
        if (lane == 0) {
            fraud[node * 2 + 0] = f0 + bC2_0;
            fraud[node * 2 + 1] = f1 + bC2_1;
            #pragma unroll
            for (int j = 0; j < 5; ++j) pat[node * 5 + j] = q[j] + bP2v[j];
        }
    }
}

// ---------------- launcher --------------------------------------------------
extern "C" void kernel_launch(void* const* d_in, const int* in_sizes, int n_in,
                              void* d_out, int out_size)
{
    const float* x     = (const float*)d_in[0];
    const int*   e0    = (const int*)  d_in[1];
    const int*   e1    = (const int*)  d_in[2];
    const float* w_emb = (const float*)d_in[3];
    const float* b_emb = (const float*)d_in[4];
    const float* Wl    = (const float*)d_in[5];
    const float* bl    = (const float*)d_in[6];
    const float* Wr    = (const float*)d_in[7];
    const float* w_att = (const float*)d_in[8];
    const float* b_att = (const float*)d_in[9];
    const float* w_c1  = (const float*)d_in[10];
    const float* b_c1  = (const float*)d_in[11];
    const float* w_c2  = (const float*)d_in[12];
    const float* b_c2  = (const float*)d_in[13];
    const float* w_p1  = (const float*)d_in[14];
    const float* b_p1  = (const float*)d_in[15];
    const float* w_p2  = (const float*)d_in[16];
    const float* b_p2  = (const float*)d_in[17];

    int n = in_sizes[0] / 128; if (n > NMAX) n = NMAX;
    int E = in_sizes[1] / 2;   if (E > EMAX) E = EMAX;

    float* out_fraud = (float*)d_out;
    float* out_pat   = out_fraud + (size_t)n * 2;
    float* out_agg   = out_pat   + (size_t)n * 5;

    __half *h0, *hA, *hB, *outb, *aggm, *pw;
    int *counts, *rowptr, *cursor, *srcs, *bsums;
    cudaGetSymbolAddress((void**)&h0, g_h0);
    cudaGetSymbolAddress((void**)&hA, g_hA);
    cudaGetSymbolAddress((void**)&hB, g_hB);
    cudaGetSymbolAddress((void**)&outb, g_out);
    cudaGetSymbolAddress((void**)&aggm, g_agg);
    cudaGetSymbolAddress((void**)&pw, g_pw);
    cudaGetSymbolAddress((void**)&counts, g_counts);
    cudaGetSymbolAddress((void**)&rowptr, g_rowptr);
    cudaGetSymbolAddress((void**)&cursor, g_cursor);
    cudaGetSymbolAddress((void**)&srcs, g_srcs);
    cudaGetSymbolAddress((void**)&bsums, g_bsums);

    const int SM_HEADS = (8192 + 8192 + 128 + 320 + 64 + 64 + 2 + 5) * 4;
    cudaFuncSetAttribute(k_sage_gemm, cudaFuncAttributeMaxDynamicSharedMemorySize, SMEM_GEMM);
    cudaFuncSetAttribute(k_att_heads, cudaFuncAttributeMaxDynamicSharedMemorySize, SM_HEADS);

    const int tiles = (n + 127) / 128;
    const int n2 = 2 * n;
    const int NB2 = (n2 + 1023) / 1024;
    const size_t COFF = (size_t)NMAX * 128;       // chain-1 offset in h buffers

    // pack all weights (6 sage pairs + embedding) into fp16 [nn][k]
    k_pack<<<dim3(8, 4, 7), dim3(32, 8)>>>(Wl, Wr, w_emb, pw);

    // dual CSR build (both edge types in one pass)
    k_count<<<(2 * E + 255) / 256, 256>>>(e0, e1, counts, E, n);
    k_scan1<<<NB2, 1024>>>(counts, rowptr, bsums, n2);
    k_scan2<<<1, 256>>>(bsums, NB2, rowptr, n2);
    k_scan3<<<NB2, 1024>>>(rowptr, bsums, cursor, counts, n2);
    k_scatter<<<(2 * E + 255) / 256, 256>>>(e0, e1, cursor, srcs, E, n);

    // node embedding: relu(x @ w_emb + b_emb)  (single chain, fp32 input)
    k_sage_gemm<<<tiles, 512, SMEM_GEMM>>>(nullptr, x, nullptr,
                                           pw + 6 * 32768, nullptr,
                                           b_emb, nullptr,
                                           h0, nullptr, n, tiles, 0);

    // 3 layers, both chains batched per launch
    const __half* hin0 = h0;
    const __half* hin1 = h0;
    __half* outs0[3] = { hA,        hB,        outb };
    __half* outs1[3] = { hA + COFF, hB + COFF, outb + COFF };
    for (int l = 0; l < 3; ++l) {
        const __half* pw0 = pw + (size_t)l * 32768;            // et=0, layer l
        const __half* pw1 = pw + (size_t)(3 + l) * 32768;      // et=1, layer l
        const float*  bl0 = bl + (size_t)l * 128;
        const float*  bl1 = bl + (size_t)(3 + l) * 128;
        k_gather<<<(n2 + 15) / 16, 512>>>(hin0, hin1, srcs, rowptr, aggm, n);
        k_sage_gemm<<<2 * tiles, 512, SMEM_GEMM>>>(aggm, hin0, hin1,
                                                   pw0, pw1, bl0, bl1,
                                                   outs0[l], outs1[l],
                                                   n, tiles, 1);
        hin0 = outs0[l];
        hin1 = outs1[l];
    }

    k_att_heads<<<592, 256, SM_HEADS>>>(outb, outb + COFF, w_att, b_att,
                                        w_c1, b_c1, w_c2, b_c2,
                                        w_p1, b_p1, w_p2, b_p2,
                                        (float4*)out_agg, out_fraud, out_pat, n);
}

// round 16
// speedup vs baseline: 1.0999x; 1.0999x over previous
#include <cuda_runtime.h>
#include <cuda_fp16.h>
#include <cstdint>

#define NMAX 100000
#define EMAX 1600000
#define FULLMASK 0xffffffffu

// ---------------- scratch (static device allocations; no cudaMalloc) -------
__device__ __half g_h0[NMAX * 128];
__device__ __half g_hA[2 * NMAX * 128];
__device__ __half g_hB[2 * NMAX * 128];
__device__ __half g_out[2 * NMAX * 128];
__device__ __half g_agg[2 * NMAX * 128];
__device__ __half g_pw[7 * 128 * 256];      // packed fp16 weights [g][nn][k]
__device__ int    g_counts[2 * NMAX];
__device__ int    g_rowptr[2 * NMAX + 1];
__device__ int    g_cursor[2 * NMAX];
__device__ int    g_srcs[2 * EMAX];
__device__ int    g_bsums[256];

// mma.sync m16n8k16 f16 -> f32 accum (portable, sm_80+)
__device__ __forceinline__ void mma_f16(float* d, const uint32_t* a, const uint32_t* b) {
    asm volatile(
        "mma.sync.aligned.m16n8k16.row.col.f32.f16.f16.f32 "
        "{%0,%1,%2,%3}, {%4,%5,%6,%7}, {%8,%9}, {%0,%1,%2,%3};"
        : "+f"(d[0]), "+f"(d[1]), "+f"(d[2]), "+f"(d[3])
        : "r"(a[0]), "r"(a[1]), "r"(a[2]), "r"(a[3]), "r"(b[0]), "r"(b[1]));
}

// smem geometry (halves): A[128][264] | B[128][264] | bias[128]f32
static constexpr int LDAH   = 264;
static constexpr int SMEM_GEMM = (2 * 128 * LDAH) * 2 + 128 * 4;   // 136192 B

// ---------------- weight pre-pack: fp32 [k][nn] -> fp16 [g][nn][k] ----------
__global__ void k_pack(const float* __restrict__ Wl, const float* __restrict__ Wr,
                       const float* __restrict__ w_emb, __half* __restrict__ pw)
{
    __shared__ float tile[32][33];
    const int g = blockIdx.z, k0 = blockIdx.x * 32, n0 = blockIdx.y * 32;
    const int tx = threadIdx.x, ty = threadIdx.y;
    #pragma unroll
    for (int i = 0; i < 4; ++i) {
        int k = k0 + ty + 8 * i, nn = n0 + tx;
        float v;
        if (g < 6) v = (k < 128) ? Wl[((size_t)g * 128 + k) * 128 + nn]
                                 : Wr[((size_t)g * 128 + (k - 128)) * 128 + nn];
        else       v = (k < 128) ? w_emb[(size_t)k * 128 + nn] : 0.f;
        tile[ty + 8 * i][tx] = v;
    }
    __syncthreads();
    #pragma unroll
    for (int i = 0; i < 4; ++i) {
        int k = k0 + tx, nn = n0 + ty + 8 * i;
        pw[((size_t)g * 128 + nn) * 256 + k] = __float2half_rn(tile[tx][ty + 8 * i]);
    }
}

// ---------------- dual-chain mean-aggregation gather (R14-validated) ---------
// Warp per global node (2n). MLP=16. aggm written evict-first (.cs): it is
// written once / read once, so keeping it out of L2 preserves residency of the
// hin random-read set (the 16x-reuse traffic).
__global__ __launch_bounds__(256) void k_gather(
    const __half* __restrict__ hin0, const __half* __restrict__ hin1,
    const int* __restrict__ srcs, const int* __restrict__ rowptr,
    __half* __restrict__ aggm, int n)
{
    const int lane = threadIdx.x & 31;
    const int node_g = blockIdx.x * 8 + (threadIdx.x >> 5);
    if (node_g >= 2 * n) return;
    const uint2* hb = (const uint2*)((node_g >= n) ? hin1 : hin0);  // row = 32 uint2
    const int beg = __ldg(&rowptr[node_g]);
    const int end = __ldg(&rowptr[node_g + 1]);
    float a0 = 0.f, a1 = 0.f, a2 = 0.f, a3 = 0.f;
    int e = beg;
    #pragma unroll 1
    for (; e + 16 <= end; e += 16) {
        int s[16];
        #pragma unroll
        for (int j = 0; j < 16; ++j) s[j] = __ldg(&srcs[e + j]);
        uint2 u[16];
        #pragma unroll
        for (int j = 0; j < 16; ++j) u[j] = __ldg(hb + (size_t)s[j] * 32 + lane);
        #pragma unroll
        for (int j = 0; j < 16; ++j) {
            float2 f0 = __half22float2(*(const __half2*)&u[j].x);
            float2 f1 = __half22float2(*(const __half2*)&u[j].y);
            a0 += f0.x; a1 += f0.y; a2 += f1.x; a3 += f1.y;
        }
    }
    #pragma unroll 1
    for (; e + 4 <= end; e += 4) {
        int s[4];
        #pragma unroll
        for (int j = 0; j < 4; ++j) s[j] = __ldg(&srcs[e + j]);
        uint2 u[4];
        #pragma unroll
        for (int j = 0; j < 4; ++j) u[j] = __ldg(hb + (size_t)s[j] * 32 + lane);
        #pragma unroll
        for (int j = 0; j < 4; ++j) {
            float2 f0 = __half22float2(*(const __half2*)&u[j].x);
            float2 f1 = __half22float2(*(const __half2*)&u[j].y);
            a0 += f0.x; a1 += f0.y; a2 += f1.x; a3 += f1.y;
        }
    }
    #pragma unroll 1
    for (; e < end; ++e) {
        uint2 u = __ldg(hb + (size_t)__ldg(&srcs[e]) * 32 + lane);
        float2 f0 = __half22float2(*(const __half2*)&u.x);
        float2 f1 = __half22float2(*(const __half2*)&u.y);
        a0 += f0.x; a1 += f0.y; a2 += f1.x; a3 += f1.y;
    }
    const float inv = 1.0f / fmaxf((float)(end - beg), 1.0f);
    int2 out;
    __half2 o01 = __floats2half2_rn(a0 * inv, a1 * inv);
    __half2 o23 = __floats2half2_rn(a2 * inv, a3 * inv);
    out.x = *(const int*)&o01;
    out.y = *(const int*)&o23;
    __stcs((int2*)((uint2*)(aggm + (size_t)node_g * 128) + lane), out);
}

// ---------------- dual-chain fused K=256 GEMM layer (fp16 MMA) ---------------
// Grid = tiles (embed, chain0 only) or 2*tiles (dual). Per CTA: 128-node tile.
// out = relu([aggm|h] @ pwg^T + bias).  do_agg=0 -> embedding (fp32 input).
__global__ __launch_bounds__(512, 1) void k_sage_gemm(
    const __half* __restrict__ aggm,
    const void* __restrict__ h0v, const void* __restrict__ h1v,
    const __half* __restrict__ pw0, const __half* __restrict__ pw1,
    const float* __restrict__ b0, const float* __restrict__ b1,
    __half* __restrict__ out0, __half* __restrict__ out1,
    int n, int tiles, int do_agg)
{
    extern __shared__ __align__(16) char smem_raw[];
    __half* sA = (__half*)smem_raw;                 // [128][264]
    __half* sB = sA + 128 * LDAH;                   // [128][264]
    float*  sBias = (float*)(sB + 128 * LDAH);      // [128]
    const int tid = threadIdx.x;
    const int wid = tid >> 5;
    const int lane = tid & 31;

    int tile = blockIdx.x, chain = 0;
    if (tile >= tiles) { chain = 1; tile -= tiles; }
    const __half* pwg  = chain ? pw1 : pw0;
    const float*  bias = chain ? b1 : b0;
    const void*   hroot_v = chain ? h1v : h0v;
    __half*       hout = chain ? out1 : out0;

    // B copy: coalesced uint4, 128 rows x 32 chunks
    {
        const uint4* pw4 = (const uint4*)pwg;
        #pragma unroll
        for (int i = tid; i < 4096; i += 512) {
            int row = i >> 5, c = i & 31;
            ((uint4*)(sB + row * LDAH))[c] = __ldg(pw4 + i);
        }
    }
    if (tid < 128) sBias[tid] = bias[tid];

    // A staging: warp owns 8 rows; batch ALL loads first (MLP~16), then store
    {
        uint2 ua[8], uh[8];
        #pragma unroll
        for (int i = 0; i < 8; ++i) {
            const int node = tile * 128 + wid * 8 + i;
            ua[i] = make_uint2(0u, 0u); uh[i] = make_uint2(0u, 0u);
            if (node < n) {
                if (do_agg) {
                    int2 t = __ldcs((const int2*)(aggm + (size_t)(chain * n + node) * 128) + lane);
                    ua[i] = make_uint2((uint32_t)t.x, (uint32_t)t.y);
                    uh[i] = __ldg((const uint2*)((const __half*)hroot_v + (size_t)node * 128) + lane);
                } else {
                    const float4 v = __ldcs((const float4*)hroot_v + (size_t)node * 32 + lane);
                    *(__half2*)&ua[i].x = __floats2half2_rn(v.x, v.y);
                    *(__half2*)&ua[i].y = __floats2half2_rn(v.z, v.w);
                }
            }
        }
        #pragma unroll
        for (int i = 0; i < 8; ++i) {
            const int row = wid * 8 + i;
            ((uint2*)(sA + row * LDAH))[lane] = ua[i];          // cols 0..127 (mean)
            ((uint2*)(sA + row * LDAH + 128))[lane] = uh[i];    // cols 128..255 (root)
        }
    }
    __syncthreads();

    // GEMM: warp wid -> rows (wid&3)*32.., cols (wid>>2)*32..; K=256
    const int wm = wid & 3;
    const int wn = wid >> 2;
    const int tr = lane >> 2;
    const int tc = lane & 3;
    float C[2][4][4];
    #pragma unroll
    for (int mt = 0; mt < 2; ++mt)
        #pragma unroll
        for (int nt = 0; nt < 4; ++nt)
            #pragma unroll
            for (int q = 0; q < 4; ++q) C[mt][nt][q] = 0.f;

    #pragma unroll 4
    for (int ks = 0; ks < 16; ++ks) {
        const int kb = ks * 16 + 2 * tc;
        uint32_t af[2][4], bf[4][2];
        #pragma unroll
        for (int mt = 0; mt < 2; ++mt) {
            const __half* p = sA + (wm * 32 + mt * 16 + tr) * LDAH + kb;
            af[mt][0] = *(const uint32_t*)(p);
            af[mt][1] = *(const uint32_t*)(p + 8 * LDAH);
            af[mt][2] = *(const uint32_t*)(p + 8);
            af[mt][3] = *(const uint32_t*)(p + 8 * LDAH + 8);
        }
        #pragma unroll
        for (int nt = 0; nt < 4; ++nt) {
            const __half* p = sB + (wn * 32 + nt * 8 + tr) * LDAH + kb;
            bf[nt][0] = *(const uint32_t*)(p);
            bf[nt][1] = *(const uint32_t*)(p + 8);
        }
        #pragma unroll
        for (int mt = 0; mt < 2; ++mt)
            #pragma unroll
            for (int nt = 0; nt < 4; ++nt)
                mma_f16(C[mt][nt], af[mt], bf[nt]);
    }

    // epilogue: bias + relu -> fp16
    #pragma unroll
    for (int mt = 0; mt < 2; ++mt) {
        int r0i = wm * 32 + mt * 16 + tr;
        int nd0 = tile * 128 + r0i;
        int nd1 = nd0 + 8;
        #pragma unroll
        for (int nt = 0; nt < 4; ++nt) {
            int col = wn * 32 + nt * 8 + tc * 2;
            float bb0 = sBias[col], bb1 = sBias[col + 1];
            if (nd0 < n) {
                __half2 v = __floats2half2_rn(fmaxf(C[mt][nt][0] + bb0, 0.f),
                                              fmaxf(C[mt][nt][1] + bb1, 0.f));
                *(__half2*)(hout + (size_t)nd0 * 128 + col) = v;
            }
            if (nd1 < n) {
                __half2 v = __floats2half2_rn(fmaxf(C[mt][nt][2] + bb0, 0.f),
                                              fmaxf(C[mt][nt][3] + bb1, 0.f));
                *(__half2*)(hout + (size_t)nd1 * 128 + col) = v;
            }
        }
    }
}

// ---------------- dual CSR build: count + 3-stage scan + scatter -------------
__global__ void k_count(const int* __restrict__ e0, const int* __restrict__ e1,
                        int* __restrict__ counts, int E, int n)
{
    int i = blockIdx.x * blockDim.x + threadIdx.x;
    if (i < E)          atomicAdd(&counts[__ldg(&e0[E + i])], 1);
    else if (i < 2 * E) atomicAdd(&counts[n + __ldg(&e1[E + (i - E)])], 1);
}

__global__ __launch_bounds__(1024) void k_scan1(
    const int* __restrict__ counts, int* __restrict__ rowptr,
    int* __restrict__ bsums, int n2)
{
    __shared__ int s[1024];
    int i = blockIdx.x * 1024 + threadIdx.x;
    int v = (i < n2) ? counts[i] : 0;
    s[threadIdx.x] = v;
    __syncthreads();
    #pragma unroll
    for (int off = 1; off < 1024; off <<= 1) {
        int t = (threadIdx.x >= off) ? s[threadIdx.x - off] : 0;
        __syncthreads();
        s[threadIdx.x] += t;
        __syncthreads();
    }
    if (i < n2) rowptr[i] = s[threadIdx.x] - v;
    if (threadIdx.x == 1023) bsums[blockIdx.x] = s[1023];
}

__global__ __launch_bounds__(256) void k_scan2(int* __restrict__ bsums, int nb,
                                               int* __restrict__ rowptr, int n2)
{
    __shared__ int s[256];
    int t = threadIdx.x;
    int v = (t < nb) ? bsums[t] : 0;
    s[t] = v;
    __syncthreads();
    #pragma unroll
    for (int off = 1; off < 256; off <<= 1) {
        int u = (t >= off) ? s[t - off] : 0;
        __syncthreads();
        s[t] += u;
        __syncthreads();
    }
    if (t < nb) bsums[t] = s[t] - v;            // exclusive
    if (t == nb - 1) rowptr[n2] = s[t];
}

__global__ void k_scan3(int* __restrict__ rowptr, const int* __restrict__ bsums,
                        int* __restrict__ cursor, int* __restrict__ counts, int n2)
{
    int i = blockIdx.x * 1024 + threadIdx.x;
    if (i < n2) {
        int v = rowptr[i] + bsums[blockIdx.x];
        rowptr[i] = v;
        cursor[i] = v;
        counts[i] = 0;          // restore invariant for next graph replay
    }
}

__global__ void k_scatter(const int* __restrict__ e0, const int* __restrict__ e1,
                          int* __restrict__ cursor, int* __restrict__ srcs,
                          int E, int n)
{
    int i = blockIdx.x * blockDim.x + threadIdx.x;
    if (i < E) {
        int d = __ldg(&e0[E + i]);
        int p = atomicAdd(&cursor[d], 1);
        srcs[p] = __ldg(&e0[i]);
    } else if (i < 2 * E) {
        int j = i - E;
        int d = __ldg(&e1[E + j]);
        int p = atomicAdd(&cursor[n + d], 1);
        srcs[p] = __ldg(&e1[j]);
    }
}

// ---------------- fused attention combine + classifier/pattern heads --------
__global__ __launch_bounds__(256) void k_att_heads(
    const __half* __restrict__ o0, const __half* __restrict__ o1,
    const float* __restrict__ watt, const float* __restrict__ batt,
    const float* __restrict__ wc1, const float* __restrict__ bc1,
    const float* __restrict__ wc2, const float* __restrict__ bc2,
    const float* __restrict__ wp1, const float* __restrict__ bp1,
    const float* __restrict__ wp2, const float* __restrict__ bp2,
    float4* __restrict__ agg, float* __restrict__ fraud, float* __restrict__ pat,
    int n)
{
    extern __shared__ float sm[];
    float* sC1 = sm;
    float* sP1 = sC1 + 8192;
    float* sC2 = sP1 + 8192;
    float* sP2 = sC2 + 128;
    float* sBC1 = sP2 + 320;
    float* sBP1 = sBC1 + 64;
    float* sBC2 = sBP1 + 64;
    float* sBP2 = sBC2 + 2;
    for (int i = threadIdx.x; i < 8192; i += blockDim.x) { sC1[i] = wc1[i]; sP1[i] = wp1[i]; }
    for (int i = threadIdx.x; i < 128;  i += blockDim.x) sC2[i] = wc2[i];
    for (int i = threadIdx.x; i < 320;  i += blockDim.x) sP2[i] = wp2[i];
    for (int i = threadIdx.x; i < 64;   i += blockDim.x) { sBC1[i] = bc1[i]; sBP1[i] = bp1[i]; }
    if (threadIdx.x < 2) sBC2[threadIdx.x] = bc2[threadIdx.x];
    if (threadIdx.x < 5) sBP2[threadIdx.x] = bp2[threadIdx.x];
    __syncthreads();

    const int lane = threadIdx.x & 31;
    const int gw = blockIdx.x * (blockDim.x >> 5) + (threadIdx.x >> 5);
    const int nw = gridDim.x * (blockDim.x >> 5);
    const float2* sC1v = (const float2*)sC1;
    const float2* sP1v = (const float2*)sP1;

    const int k0 = lane * 4;
    float wa0[4], wa1[4], wb0[4], wb1[4];
    #pragma unroll
    for (int c = 0; c < 4; ++c) {
        wa0[c] = __ldg(&watt[(k0 + c) * 2 + 0]);
        wa1[c] = __ldg(&watt[(k0 + c) * 2 + 1]);
        wb0[c] = __ldg(&watt[(128 + k0 + c) * 2 + 0]);
        wb1[c] = __ldg(&watt[(128 + k0 + c) * 2 + 1]);
    }
    const float bt0 = __ldg(&batt[0]), bt1 = __ldg(&batt[1]);

    const int hA = 2 * lane, hBb = 2 * lane + 1;
    const float c2a0 = sC2[hA * 2 + 0], c2a1 = sC2[hA * 2 + 1];
    const float c2b0 = sC2[hBb * 2 + 0], c2b1 = sC2[hBb * 2 + 1];
    float p2a[5], p2b[5];
    #pragma unroll
    for (int j = 0; j < 5; ++j) { p2a[j] = sP2[hA * 5 + j]; p2b[j] = sP2[hBb * 5 + j]; }
    const float bC1a = sBC1[hA], bC1b = sBC1[hBb];
    const float bP1a = sBP1[hA], bP1b = sBP1[hBb];
    const float bC2_0 = sBC2[0], bC2_1 = sBC2[1];
    float bP2v[5];
    #pragma unroll
    for (int j = 0; j < 5; ++j) bP2v[j] = sBP2[j];

    for (int node = gw; node < n; node += nw) {
        int2 ta = __ldcs((const int2*)(o0 + (size_t)node * 128) + lane);
        int2 tb = __ldcs((const int2*)(o1 + (size_t)node * 128) + lane);
        uint2 ua = make_uint2((uint32_t)ta.x, (uint32_t)ta.y);
        uint2 ub = make_uint2((uint32_t)tb.x, (uint32_t)tb.y);
        float2 a01 = __half22float2(*(const __half2*)&ua.x);
        float2 a23 = __half22float2(*(const __half2*)&ua.y);
        float2 b01 = __half22float2(*(const __half2*)&ub.x);
        float2 b23 = __half22float2(*(const __half2*)&ub.y);
        float p0 = a01.x * wa0[0] + a01.y * wa0[1] + a23.x * wa0[2] + a23.y * wa0[3]
                 + b01.x * wb0[0] + b01.y * wb0[1] + b23.x * wb0[2] + b23.y * wb0[3];
        float p1 = a01.x * wa1[0] + a01.y * wa1[1] + a23.x * wa1[2] + a23.y * wa1[3]
                 + b01.x * wb1[0] + b01.y * wb1[1] + b23.x * wb1[2] + b23.y * wb1[3];
        #pragma unroll
        for (int off = 16; off; off >>= 1) {
            p0 += __shfl_xor_sync(FULLMASK, p0, off);
            p1 += __shfl_xor_sync(FULLMASK, p1, off);
        }
        float z0 = p0 + bt0, z1 = p1 + bt1;
        float m = fmaxf(z0, z1);
        float e0 = expf(z0 - m), e1 = expf(z1 - m);
        float inv = 1.0f / (e0 + e1);
        float w0 = e0 * inv, w1 = e1 * inv;
        float4 ar;
        ar.x = w0 * a01.x + w1 * b01.x;
        ar.y = w0 * a01.y + w1 * b01.y;
        ar.z = w0 * a23.x + w1 * b23.x;
        ar.w = w0 * a23.y + w1 * b23.y;
        agg[node * 32 + lane] = ar;

        float hc0 = bC1a, hc1 = bC1b, hp0 = bP1a, hp1 = bP1b;
        #pragma unroll 4
        for (int kk = 0; kk < 32; ++kk) {
            float av[4];
            av[0] = __shfl_sync(FULLMASK, ar.x, kk);
            av[1] = __shfl_sync(FULLMASK, ar.y, kk);
            av[2] = __shfl_sync(FULLMASK, ar.z, kk);
            av[3] = __shfl_sync(FULLMASK, ar.w, kk);
            #pragma unroll
            for (int j = 0; j < 4; ++j) {
                int k = kk * 4 + j;
                float2 wc = sC1v[k * 32 + lane];
                float2 wp = sP1v[k * 32 + lane];
                hc0 += av[j] * wc.x; hc1 += av[j] * wc.y;
                hp0 += av[j] * wp.x; hp1 += av[j] * wp.y;
            }
        }
        hc0 = fmaxf(hc0, 0.f); hc1 = fmaxf(hc1, 0.f);
        hp0 = fmaxf(hp0, 0.f); hp1 = fmaxf(hp1, 0.f);

        float f0 = hc0 * c2a0 + hc1 * c2b0;
        float f1 = hc0 * c2a1 + hc1 * c2b1;
        float q[5];
        #pragma unroll
        for (int j = 0; j < 5; ++j) q[j] = hp0 * p2a[j] + hp1 * p2b[j];
        #pragma unroll
        for (int off = 16; off; off >>= 1) {
            f0 += __shfl_xor_sync(FULLMASK, f0, off);
            f1 += __shfl_xor_sync(FULLMASK, f1, off);
            #pragma unroll
            for (int j = 0; j < 5; ++j) q[j] += __shfl_xor_sync(FULLMASK, q[j], off);
        }
        if (lane == 0) {
            fraud[node * 2 + 0] = f0 + bC2_0;
            fraud[node * 2 + 1] = f1 + bC2_1;
            #pragma unroll
            for (int j = 0; j < 5; ++j) pat[node * 5 + j] = q[j] + bP2v[j];
        }
    }
}

// ---------------- launcher --------------------------------------------------
extern "C" void kernel_launch(void* const* d_in, const int* in_sizes, int n_in,
                              void* d_out, int out_size)
{
    const float* x     = (const float*)d_in[0];
    const int*   e0    = (const int*)  d_in[1];
    const int*   e1    = (const int*)  d_in[2];
    const float* w_emb = (const float*)d_in[3];
    const float* b_emb = (const float*)d_in[4];
    const float* Wl    = (const float*)d_in[5];
    const float* bl    = (const float*)d_in[6];
    const float* Wr    = (const float*)d_in[7];
    const float* w_att = (const float*)d_in[8];
    const float* b_att = (const float*)d_in[9];
    const float* w_c1  = (const float*)d_in[10];
    const float* b_c1  = (const float*)d_in[11];
    const float* w_c2  = (const float*)d_in[12];
    const float* b_c2  = (const float*)d_in[13];
    const float* w_p1  = (const float*)d_in[14];
    const float* b_p1  = (const float*)d_in[15];
    const float* w_p2  = (const float*)d_in[16];
    const float* b_p2  = (const float*)d_in[17];

    int n = in_sizes[0] / 128; if (n > NMAX) n = NMAX;
    int E = in_sizes[1] / 2;   if (E > EMAX) E = EMAX;

    float* out_fraud = (float*)d_out;
    float* out_pat   = out_fraud + (size_t)n * 2;
    float* out_agg   = out_pat   + (size_t)n * 5;

    __half *h0, *hA, *hB, *outb, *aggm, *pw;
    int *counts, *rowptr, *cursor, *srcs, *bsums;
    cudaGetSymbolAddress((void**)&h0, g_h0);
    cudaGetSymbolAddress((void**)&hA, g_hA);
    cudaGetSymbolAddress((void**)&hB, g_hB);
    cudaGetSymbolAddress((void**)&outb, g_out);
    cudaGetSymbolAddress((void**)&aggm, g_agg);
    cudaGetSymbolAddress((void**)&pw, g_pw);
    cudaGetSymbolAddress((void**)&counts, g_counts);
    cudaGetSymbolAddress((void**)&rowptr, g_rowptr);
    cudaGetSymbolAddress((void**)&cursor, g_cursor);
    cudaGetSymbolAddress((void**)&srcs, g_srcs);
    cudaGetSymbolAddress((void**)&bsums, g_bsums);

    const int SM_HEADS = (8192 + 8192 + 128 + 320 + 64 + 64 + 2 + 5) * 4;
    cudaFuncSetAttribute(k_sage_gemm, cudaFuncAttributeMaxDynamicSharedMemorySize, SMEM_GEMM);
    cudaFuncSetAttribute(k_att_heads, cudaFuncAttributeMaxDynamicSharedMemorySize, SM_HEADS);

    const int tiles = (n + 127) / 128;
    const int n2 = 2 * n;
    const int NB2 = (n2 + 1023) / 1024;
    const size_t COFF = (size_t)NMAX * 128;       // chain-1 offset in h buffers

    // pack all weights (6 sage pairs + embedding) into fp16 [nn][k]
    k_pack<<<dim3(8, 4, 7), dim3(32, 8)>>>(Wl, Wr, w_emb, pw);

    // dual CSR build (both edge types in one pass)
    k_count<<<(2 * E + 255) / 256, 256>>>(e0, e1, counts, E, n);
    k_scan1<<<NB2, 1024>>>(counts, rowptr, bsums, n2);
    k_scan2<<<1, 256>>>(bsums, NB2, rowptr, n2);
    k_scan3<<<NB2, 1024>>>(rowptr, bsums, cursor, counts, n2);
    k_scatter<<<(2 * E + 255) / 256, 256>>>(e0, e1, cursor, srcs, E, n);

    // node embedding: relu(x @ w_emb + b_emb)  (single chain, fp32 input)
    k_sage_gemm<<<tiles, 512, SMEM_GEMM>>>(nullptr, x, nullptr,
                                           pw + 6 * 32768, nullptr,
                                           b_emb, nullptr,
                                           h0, nullptr, n, tiles, 0);

    // 3 layers, both chains batched per launch
    const __half* hin0 = h0;
    const __half* hin1 = h0;
    __half* outs0[3] = { hA,        hB,        outb };
    __half* outs1[3] = { hA + COFF, hB + COFF, outb + COFF };
    for (int l = 0; l < 3; ++l) {
        const __half* pw0 = pw + (size_t)l * 32768;            // et=0, layer l
        const __half* pw1 = pw + (size_t)(3 + l) * 32768;      // et=1, layer l
        const float*  bl0 = bl + (size_t)l * 128;
        const float*  bl1 = bl + (size_t)(3 + l) * 128;
        k_gather<<<(n2 + 7) / 8, 256>>>(hin0, hin1, srcs, rowptr, aggm, n);
        k_sage_gemm<<<2 * tiles, 512, SMEM_GEMM>>>(aggm, hin0, hin1,
                                                   pw0, pw1, bl0, bl1,
                                                   outs0[l], outs1[l],
                                                   n, tiles, 1);
        hin0 = outs0[l];
        hin1 = outs1[l];
    }

    k_att_heads<<<592, 256, SM_HEADS>>>(outb, outb + COFF, w_att, b_att,
                                        w_c1, b_c1, w_c2, b_c2,
                                        w_p1, b_p1, w_p2, b_p2,
                                        (float4*)out_agg, out_fraud, out_pat, n);
}

// round 17
// speedup vs baseline: 1.1115x; 1.0106x over previous
#include <cuda_runtime.h>
#include <cuda_fp16.h>
#include <cstdint>

#define NMAX 100000
#define EMAX 1600000
#define FULLMASK 0xffffffffu

// ---------------- scratch (static device allocations; no cudaMalloc) -------
__device__ __half g_h0[NMAX * 128];
__device__ __half g_hA[2 * NMAX * 128];
__device__ __half g_hB[2 * NMAX * 128];
__device__ __half g_out[2 * NMAX * 128];
__device__ __half g_agg[2 * NMAX * 128];
__device__ __half g_pw[7 * 128 * 256];      // packed fp16 weights [g][nn][k]
__device__ int    g_counts[2 * NMAX];
__device__ int    g_rowptr[2 * NMAX + 1];
__device__ int    g_cursor[2 * NMAX];
__device__ int    g_srcs[2 * EMAX];
__device__ int    g_bsums[256];

// mma.sync m16n8k16 f16 -> f32 accum (portable, sm_80+)
__device__ __forceinline__ void mma_f16(float* d, const uint32_t* a, const uint32_t* b) {
    asm volatile(
        "mma.sync.aligned.m16n8k16.row.col.f32.f16.f16.f32 "
        "{%0,%1,%2,%3}, {%4,%5,%6,%7}, {%8,%9}, {%0,%1,%2,%3};"
        : "+f"(d[0]), "+f"(d[1]), "+f"(d[2]), "+f"(d[3])
        : "r"(a[0]), "r"(a[1]), "r"(a[2]), "r"(a[3]), "r"(b[0]), "r"(b[1]));
}

// smem geometry (halves): A[128][264] | B[128][264] | bias[128]f32
static constexpr int LDAH   = 264;
static constexpr int SMEM_GEMM = (2 * 128 * LDAH) * 2 + 128 * 4;   // 136192 B

// ---------------- weight pre-pack: fp32 [k][nn] -> fp16 [g][nn][k] ----------
__global__ void k_pack(const float* __restrict__ Wl, const float* __restrict__ Wr,
                       const float* __restrict__ w_emb, __half* __restrict__ pw)
{
    __shared__ float tile[32][33];
    const int g = blockIdx.z, k0 = blockIdx.x * 32, n0 = blockIdx.y * 32;
    const int tx = threadIdx.x, ty = threadIdx.y;
    #pragma unroll
    for (int i = 0; i < 4; ++i) {
        int k = k0 + ty + 8 * i, nn = n0 + tx;
        float v;
        if (g < 6) v = (k < 128) ? Wl[((size_t)g * 128 + k) * 128 + nn]
                                 : Wr[((size_t)g * 128 + (k - 128)) * 128 + nn];
        else       v = (k < 128) ? w_emb[(size_t)k * 128 + nn] : 0.f;
        tile[ty + 8 * i][tx] = v;
    }
    __syncthreads();
    #pragma unroll
    for (int i = 0; i < 4; ++i) {
        int k = k0 + tx, nn = n0 + ty + 8 * i;
        pw[((size_t)g * 128 + nn) * 256 + k] = __float2half_rn(tile[tx][ty + 8 * i]);
    }
}

// ---------------- dual-chain mean-aggregation gather (R14-validated) ---------
// Warp per global node (2n). MLP=16. aggm written evict-first (.cs): it is
// written once / read once, so keeping it out of L2 preserves residency of the
// hin random-read set (the 16x-reuse traffic).
__global__ __launch_bounds__(256) void k_gather(
    const __half* __restrict__ hin0, const __half* __restrict__ hin1,
    const int* __restrict__ srcs, const int* __restrict__ rowptr,
    __half* __restrict__ aggm, int n)
{
    const int lane = threadIdx.x & 31;
    const int node_g = blockIdx.x * 8 + (threadIdx.x >> 5);
    if (node_g >= 2 * n) return;
    const uint2* hb = (const uint2*)((node_g >= n) ? hin1 : hin0);  // row = 32 uint2
    const int beg = __ldg(&rowptr[node_g]);
    const int end = __ldg(&rowptr[node_g + 1]);
    float a0 = 0.f, a1 = 0.f, a2 = 0.f, a3 = 0.f;
    int e = beg;
    #pragma unroll 1
    for (; e + 16 <= end; e += 16) {
        int s[16];
        #pragma unroll
        for (int j = 0; j < 16; ++j) s[j] = __ldg(&srcs[e + j]);
        uint2 u[16];
        #pragma unroll
        for (int j = 0; j < 16; ++j) u[j] = __ldg(hb + (size_t)s[j] * 32 + lane);
        #pragma unroll
        for (int j = 0; j < 16; ++j) {
            float2 f0 = __half22float2(*(const __half2*)&u[j].x);
            float2 f1 = __half22float2(*(const __half2*)&u[j].y);
            a0 += f0.x; a1 += f0.y; a2 += f1.x; a3 += f1.y;
        }
    }
    #pragma unroll 1
    for (; e + 4 <= end; e += 4) {
        int s[4];
        #pragma unroll
        for (int j = 0; j < 4; ++j) s[j] = __ldg(&srcs[e + j]);
        uint2 u[4];
        #pragma unroll
        for (int j = 0; j < 4; ++j) u[j] = __ldg(hb + (size_t)s[j] * 32 + lane);
        #pragma unroll
        for (int j = 0; j < 4; ++j) {
            float2 f0 = __half22float2(*(const __half2*)&u[j].x);
            float2 f1 = __half22float2(*(const __half2*)&u[j].y);
            a0 += f0.x; a1 += f0.y; a2 += f1.x; a3 += f1.y;
        }
    }
    #pragma unroll 1
    for (; e < end; ++e) {
        uint2 u = __ldg(hb + (size_t)__ldg(&srcs[e]) * 32 + lane);
        float2 f0 = __half22float2(*(const __half2*)&u.x);
        float2 f1 = __half22float2(*(const __half2*)&u.y);
        a0 += f0.x; a1 += f0.y; a2 += f1.x; a3 += f1.y;
    }
    const float inv = 1.0f / fmaxf((float)(end - beg), 1.0f);
    int2 out;
    __half2 o01 = __floats2half2_rn(a0 * inv, a1 * inv);
    __half2 o23 = __floats2half2_rn(a2 * inv, a3 * inv);
    out.x = *(const int*)&o01;
    out.y = *(const int*)&o23;
    __stcs((int2*)((uint2*)(aggm + (size_t)node_g * 128) + lane), out);
}

// ---------------- dual-chain fused K=256 GEMM layer (fp16 MMA) ---------------
// Grid = tiles (embed, chain0 only) or 2*tiles (dual). Per CTA: 128-node tile.
// out = relu([aggm|h] @ pwg^T + bias).  do_agg=0 -> embedding (fp32 input).
__global__ __launch_bounds__(512, 1) void k_sage_gemm(
    const __half* __restrict__ aggm,
    const void* __restrict__ h0v, const void* __restrict__ h1v,
    const __half* __restrict__ pw0, const __half* __restrict__ pw1,
    const float* __restrict__ b0, const float* __restrict__ b1,
    __half* __restrict__ out0, __half* __restrict__ out1,
    int n, int tiles, int do_agg)
{
    extern __shared__ __align__(16) char smem_raw[];
    __half* sA = (__half*)smem_raw;                 // [128][264]
    __half* sB = sA + 128 * LDAH;                   // [128][264]
    float*  sBias = (float*)(sB + 128 * LDAH);      // [128]
    const int tid = threadIdx.x;
    const int wid = tid >> 5;
    const int lane = tid & 31;

    int tile = blockIdx.x, chain = 0;
    if (tile >= tiles) { chain = 1; tile -= tiles; }
    const __half* pwg  = chain ? pw1 : pw0;
    const float*  bias = chain ? b1 : b0;
    const void*   hroot_v = chain ? h1v : h0v;
    __half*       hout = chain ? out1 : out0;

    // B copy: coalesced uint4, 128 rows x 32 chunks
    {
        const uint4* pw4 = (const uint4*)pwg;
        #pragma unroll
        for (int i = tid; i < 4096; i += 512) {
            int row = i >> 5, c = i & 31;
            ((uint4*)(sB + row * LDAH))[c] = __ldg(pw4 + i);
        }
    }
    if (tid < 128) sBias[tid] = bias[tid];

    // A staging: warp owns 8 rows; batch ALL loads first (MLP~16), then store.
    // hin (root rows) is dead after this read -> evict-first keeps 'out' of the
    // previous GEMM resident for the NEXT gather's random reads.
    {
        uint2 ua[8], uh[8];
        #pragma unroll
        for (int i = 0; i < 8; ++i) {
            const int node = tile * 128 + wid * 8 + i;
            ua[i] = make_uint2(0u, 0u); uh[i] = make_uint2(0u, 0u);
            if (node < n) {
                if (do_agg) {
                    int2 t = __ldcs((const int2*)(aggm + (size_t)(chain * n + node) * 128) + lane);
                    ua[i] = make_uint2((uint32_t)t.x, (uint32_t)t.y);
                    int2 r = __ldcs((const int2*)((const __half*)hroot_v + (size_t)node * 128) + lane);
                    uh[i] = make_uint2((uint32_t)r.x, (uint32_t)r.y);
                } else {
                    const float4 v = __ldcs((const float4*)hroot_v + (size_t)node * 32 + lane);
                    *(__half2*)&ua[i].x = __floats2half2_rn(v.x, v.y);
                    *(__half2*)&ua[i].y = __floats2half2_rn(v.z, v.w);
                }
            }
        }
        #pragma unroll
        for (int i = 0; i < 8; ++i) {
            const int row = wid * 8 + i;
            ((uint2*)(sA + row * LDAH))[lane] = ua[i];          // cols 0..127 (mean)
            ((uint2*)(sA + row * LDAH + 128))[lane] = uh[i];    // cols 128..255 (root)
        }
    }
    __syncthreads();

    // GEMM: warp wid -> rows (wid&3)*32.., cols (wid>>2)*32..; K=256
    const int wm = wid & 3;
    const int wn = wid >> 2;
    const int tr = lane >> 2;
    const int tc = lane & 3;
    float C[2][4][4];
    #pragma unroll
    for (int mt = 0; mt < 2; ++mt)
        #pragma unroll
        for (int nt = 0; nt < 4; ++nt)
            #pragma unroll
            for (int q = 0; q < 4; ++q) C[mt][nt][q] = 0.f;

    #pragma unroll 4
    for (int ks = 0; ks < 16; ++ks) {
        const int kb = ks * 16 + 2 * tc;
        uint32_t af[2][4], bf[4][2];
        #pragma unroll
        for (int mt = 0; mt < 2; ++mt) {
            const __half* p = sA + (wm * 32 + mt * 16 + tr) * LDAH + kb;
            af[mt][0] = *(const uint32_t*)(p);
            af[mt][1] = *(const uint32_t*)(p + 8 * LDAH);
            af[mt][2] = *(const uint32_t*)(p + 8);
            af[mt][3] = *(const uint32_t*)(p + 8 * LDAH + 8);
        }
        #pragma unroll
        for (int nt = 0; nt < 4; ++nt) {
            const __half* p = sB + (wn * 32 + nt * 8 + tr) * LDAH + kb;
            bf[nt][0] = *(const uint32_t*)(p);
            bf[nt][1] = *(const uint32_t*)(p + 8);
        }
        #pragma unroll
        for (int mt = 0; mt < 2; ++mt)
            #pragma unroll
            for (int nt = 0; nt < 4; ++nt)
                mma_f16(C[mt][nt], af[mt], bf[nt]);
    }

    // epilogue: bias + relu -> fp16
    #pragma unroll
    for (int mt = 0; mt < 2; ++mt) {
        int r0i = wm * 32 + mt * 16 + tr;
        int nd0 = tile * 128 + r0i;
        int nd1 = nd0 + 8;
        #pragma unroll
        for (int nt = 0; nt < 4; ++nt) {
            int col = wn * 32 + nt * 8 + tc * 2;
            float bb0 = sBias[col], bb1 = sBias[col + 1];
            if (nd0 < n) {
                __half2 v = __floats2half2_rn(fmaxf(C[mt][nt][0] + bb0, 0.f),
                                              fmaxf(C[mt][nt][1] + bb1, 0.f));
                *(__half2*)(hout + (size_t)nd0 * 128 + col) = v;
            }
            if (nd1 < n) {
                __half2 v = __floats2half2_rn(fmaxf(C[mt][nt][2] + bb0, 0.f),
                                              fmaxf(C[mt][nt][3] + bb1, 0.f));
                *(__half2*)(hout + (size_t)nd1 * 128 + col) = v;
            }
        }
    }
}

// ---------------- dual CSR build: count + 3-stage scan + scatter -------------
// Vectorized: 2 edges per thread via int2 loads of the contiguous dst halves.
__global__ void k_count(const int* __restrict__ e0, const int* __restrict__ e1,
                        int* __restrict__ counts, int E, int n)
{
    const int P = E >> 1;                      // edge pairs per chain
    int i = blockIdx.x * blockDim.x + threadIdx.x;
    if (i < P) {
        int2 d = __ldg((const int2*)(e0 + E) + i);
        atomicAdd(&counts[d.x], 1);
        atomicAdd(&counts[d.y], 1);
    } else if (i < 2 * P) {
        int2 d = __ldg((const int2*)(e1 + E) + (i - P));
        atomicAdd(&counts[n + d.x], 1);
        atomicAdd(&counts[n + d.y], 1);
    } else if (E & 1) {
        if (i == 2 * P)     atomicAdd(&counts[__ldg(&e0[E + E - 1])], 1);
        if (i == 2 * P + 1) atomicAdd(&counts[n + __ldg(&e1[E + E - 1])], 1);
    }
}

__global__ __launch_bounds__(1024) void k_scan1(
    const int* __restrict__ counts, int* __restrict__ rowptr,
    int* __restrict__ bsums, int n2)
{
    __shared__ int s[1024];
    int i = blockIdx.x * 1024 + threadIdx.x;
    int v = (i < n2) ? counts[i] : 0;
    s[threadIdx.x] = v;
    __syncthreads();
    #pragma unroll
    for (int off = 1; off < 1024; off <<= 1) {
        int t = (threadIdx.x >= off) ? s[threadIdx.x - off] : 0;
        __syncthreads();
        s[threadIdx.x] += t;
        __syncthreads();
    }
    if (i < n2) rowptr[i] = s[threadIdx.x] - v;
    if (threadIdx.x == 1023) bsums[blockIdx.x] = s[1023];
}

__global__ __launch_bounds__(256) void k_scan2(int* __restrict__ bsums, int nb,
                                               int* __restrict__ rowptr, int n2)
{
    __shared__ int s[256];
    int t = threadIdx.x;
    int v = (t < nb) ? bsums[t] : 0;
    s[t] = v;
    __syncthreads();
    #pragma unroll
    for (int off = 1; off < 256; off <<= 1) {
        int u = (t >= off) ? s[t - off] : 0;
        __syncthreads();
        s[t] += u;
        __syncthreads();
    }
    if (t < nb) bsums[t] = s[t] - v;            // exclusive
    if (t == nb - 1) rowptr[n2] = s[t];
}

__global__ void k_scan3(int* __restrict__ rowptr, const int* __restrict__ bsums,
                        int* __restrict__ cursor, int* __restrict__ counts, int n2)
{
    int i = blockIdx.x * 1024 + threadIdx.x;
    if (i < n2) {
        int v = rowptr[i] + bsums[blockIdx.x];
        rowptr[i] = v;
        cursor[i] = v;
        counts[i] = 0;          // restore invariant for next graph replay
    }
}

__global__ void k_scatter(const int* __restrict__ e0, const int* __restrict__ e1,
                          int* __restrict__ cursor, int* __restrict__ srcs,
                          int E, int n)
{
    const int P = E >> 1;
    int i = blockIdx.x * blockDim.x + threadIdx.x;
    if (i < P) {
        int2 d = __ldg((const int2*)(e0 + E) + i);
        int2 s = __ldg((const int2*)e0 + i);
        srcs[atomicAdd(&cursor[d.x], 1)] = s.x;
        srcs[atomicAdd(&cursor[d.y], 1)] = s.y;
    } else if (i < 2 * P) {
        int2 d = __ldg((const int2*)(e1 + E) + (i - P));
        int2 s = __ldg((const int2*)e1 + (i - P));
        srcs[atomicAdd(&cursor[n + d.x], 1)] = s.x;
        srcs[atomicAdd(&cursor[n + d.y], 1)] = s.y;
    } else if (E & 1) {
        if (i == 2 * P) {
            int d = __ldg(&e0[E + E - 1]);
            srcs[atomicAdd(&cursor[d], 1)] = __ldg(&e0[E - 1]);
        }
        if (i == 2 * P + 1) {
            int d = __ldg(&e1[E + E - 1]);
            srcs[atomicAdd(&cursor[n + d], 1)] = __ldg(&e1[E - 1]);
        }
    }
}

// ---------------- fused attention combine + classifier/pattern heads --------
__global__ __launch_bounds__(256) void k_att_heads(
    const __half* __restrict__ o0, const __half* __restrict__ o1,
    const float* __restrict__ watt, const float* __restrict__ batt,
    const float* __restrict__ wc1, const float* __restrict__ bc1,
    const float* __restrict__ wc2, const float* __restrict__ bc2,
    const float* __restrict__ wp1, const float* __restrict__ bp1,
    const float* __restrict__ wp2, const float* __restrict__ bp2,
    float4* __restrict__ agg, float* __restrict__ fraud, float* __restrict__ pat,
    int n)
{
    extern __shared__ float sm[];
    float* sC1 = sm;
    float* sP1 = sC1 + 8192;
    float* sC2 = sP1 + 8192;
    float* sP2 = sC2 + 128;
    float* sBC1 = sP2 + 320;
    float* sBP1 = sBC1 + 64;
    float* sBC2 = sBP1 + 64;
    float* sBP2 = sBC2 + 2;
    for (int i = threadIdx.x; i < 8192; i += blockDim.x) { sC1[i] = wc1[i]; sP1[i] = wp1[i]; }
    for (int i = threadIdx.x; i < 128;  i += blockDim.x) sC2[i] = wc2[i];
    for (int i = threadIdx.x; i < 320;  i += blockDim.x) sP2[i] = wp2[i];
    for (int i = threadIdx.x; i < 64;   i += blockDim.x) { sBC1[i] = bc1[i]; sBP1[i] = bp1[i]; }
    if (threadIdx.x < 2) sBC2[threadIdx.x] = bc2[threadIdx.x];
    if (threadIdx.x < 5) sBP2[threadIdx.x] = bp2[threadIdx.x];
    __syncthreads();

    const int lane = threadIdx.x & 31;
    const int gw = blockIdx.x * (blockDim.x >> 5) + (threadIdx.x >> 5);
    const int nw = gridDim.x * (blockDim.x >> 5);
    const float2* sC1v = (const float2*)sC1;
    const float2* sP1v = (const float2*)sP1;

    const int k0 = lane * 4;
    float wa0[4], wa1[4], wb0[4], wb1[4];
    #pragma unroll
    for (int c = 0; c < 4; ++c) {
        wa0[c] = __ldg(&watt[(k0 + c) * 2 + 0]);
        wa1[c] = __ldg(&watt[(k0 + c) * 2 + 1]);
        wb0[c] = __ldg(&watt[(128 + k0 + c) * 2 + 0]);
        wb1[c] = __ldg(&watt[(128 + k0 + c) * 2 + 1]);
    }
    const float bt0 = __ldg(&batt[0]), bt1 = __ldg(&batt[1]);

    const int hA = 2 * lane, hBb = 2 * lane + 1;
    const float c2a0 = sC2[hA * 2 + 0], c2a1 = sC2[hA * 2 + 1];
    const float c2b0 = sC2[hBb * 2 + 0], c2b1 = sC2[hBb * 2 + 1];
    float p2a[5], p2b[5];
    #pragma unroll
    for (int j = 0; j < 5; ++j) { p2a[j] = sP2[hA * 5 + j]; p2b[j] = sP2[hBb * 5 + j]; }
    const float bC1a = sBC1[hA], bC1b = sBC1[hBb];
    const float bP1a = sBP1[hA], bP1b = sBP1[hBb];
    const float bC2_0 = sBC2[0], bC2_1 = sBC2[1];
    float bP2v[5];
    #pragma unroll
    for (int j = 0; j < 5; ++j) bP2v[j] = sBP2[j];

    for (int node = gw; node < n; node += nw) {
        int2 ta = __ldcs((const int2*)(o0 + (size_t)node * 128) + lane);
        int2 tb = __ldcs((const int2*)(o1 + (size_t)node * 128) + lane);
        uint2 ua = make_uint2((uint32_t)ta.x, (uint32_t)ta.y);
        uint2 ub = make_uint2((uint32_t)tb.x, (uint32_t)tb.y);
        float2 a01 = __half22float2(*(const __half2*)&ua.x);
        float2 a23 = __half22float2(*(const __half2*)&ua.y);
        float2 b01 = __half22float2(*(const __half2*)&ub.x);
        float2 b23 = __half22float2(*(const __half2*)&ub.y);
        float p0 = a01.x * wa0[0] + a01.y * wa0[1] + a23.x * wa0[2] + a23.y * wa0[3]
                 + b01.x * wb0[0] + b01.y * wb0[1] + b23.x * wb0[2] + b23.y * wb0[3];
        float p1 = a01.x * wa1[0] + a01.y * wa1[1] + a23.x * wa1[2] + a23.y * wa1[3]
                 + b01.x * wb1[0] + b01.y * wb1[1] + b23.x * wb1[2] + b23.y * wb1[3];
        #pragma unroll
        for (int off = 16; off; off >>= 1) {
            p0 += __shfl_xor_sync(FULLMASK, p0, off);
            p1 += __shfl_xor_sync(FULLMASK, p1, off);
        }
        float z0 = p0 + bt0, z1 = p1 + bt1;
        float m = fmaxf(z0, z1);
        float e0 = expf(z0 - m), e1 = expf(z1 - m);
        float inv = 1.0f / (e0 + e1);
        float w0 = e0 * inv, w1 = e1 * inv;
        float4 ar;
        ar.x = w0 * a01.x + w1 * b01.x;
        ar.y = w0 * a01.y + w1 * b01.y;
        ar.z = w0 * a23.x + w1 * b23.x;
        ar.w = w0 * a23.y + w1 * b23.y;
        agg[node * 32 + lane] = ar;

        float hc0 = bC1a, hc1 = bC1b, hp0 = bP1a, hp1 = bP1b;
        #pragma unroll 4
        for (int kk = 0; kk < 32; ++kk) {
            float av[4];
            av[0] = __shfl_sync(FULLMASK, ar.x, kk);
            av[1] = __shfl_sync(FULLMASK, ar.y, kk);
            av[2] = __shfl_sync(FULLMASK, ar.z, kk);
            av[3] = __shfl_sync(FULLMASK, ar.w, kk);
            #pragma unroll
            for (int j = 0; j < 4; ++j) {
                int k = kk * 4 + j;
                float2 wc = sC1v[k * 32 + lane];
                float2 wp = sP1v[k * 32 + lane];
                hc0 += av[j] * wc.x; hc1 += av[j] * wc.y;
                hp0 += av[j] * wp.x; hp1 += av[j] * wp.y;
            }
        }
        hc0 = fmaxf(hc0, 0.f); hc1 = fmaxf(hc1, 0.f);
        hp0 = fmaxf(hp0, 0.f); hp1 = fmaxf(hp1, 0.f);

        float f0 = hc0 * c2a0 + hc1 * c2b0;
        float f1 = hc0 * c2a1 + hc1 * c2b1;
        float q[5];
        #pragma unroll
        for (int j = 0; j < 5; ++j) q[j] = hp0 * p2a[j] + hp1 * p2b[j];
        #pragma unroll
        for (int off = 16; off; off >>= 1) {
            f0 += __shfl_xor_sync(FULLMASK, f0, off);
            f1 += __shfl_xor_sync(FULLMASK, f1, off);
            #pragma unroll
            for (int j = 0; j < 5; ++j) q[j] += __shfl_xor_sync(FULLMASK, q[j], off);
        }
        if (lane == 0) {
            fraud[node * 2 + 0] = f0 + bC2_0;
            fraud[node * 2 + 1] = f1 + bC2_1;
            #pragma unroll
            for (int j = 0; j < 5; ++j) pat[node * 5 + j] = q[j] + bP2v[j];
        }
    }
}

// ---------------- launcher --------------------------------------------------
extern "C" void kernel_launch(void* const* d_in, const int* in_sizes, int n_in,
                              void* d_out, int out_size)
{
    const float* x     = (const float*)d_in[0];
    const int*   e0    = (const int*)  d_in[1];
    const int*   e1    = (const int*)  d_in[2];
    const float* w_emb = (const float*)d_in[3];
    const float* b_emb = (const float*)d_in[4];
    const float* Wl    = (const float*)d_in[5];
    const float* bl    = (const float*)d_in[6];
    const float* Wr    = (const float*)d_in[7];
    const float* w_att = (const float*)d_in[8];
    const float* b_att = (const float*)d_in[9];
    const float* w_c1  = (const float*)d_in[10];
    const float* b_c1  = (const float*)d_in[11];
    const float* w_c2  = (const float*)d_in[12];
    const float* b_c2  = (const float*)d_in[13];
    const float* w_p1  = (const float*)d_in[14];
    const float* b_p1  = (const float*)d_in[15];
    const float* w_p2  = (const float*)d_in[16];
    const float* b_p2  = (const float*)d_in[17];

    int n = in_sizes[0] / 128; if (n > NMAX) n = NMAX;
    int E = in_sizes[1] / 2;   if (E > EMAX) E = EMAX;

    float* out_fraud = (float*)d_out;
    float* out_pat   = out_fraud + (size_t)n * 2;
    float* out_agg   = out_pat   + (size_t)n * 5;

    __half *h0, *hA, *hB, *outb, *aggm, *pw;
    int *counts, *rowptr, *cursor, *srcs, *bsums;
    cudaGetSymbolAddress((void**)&h0, g_h0);
    cudaGetSymbolAddress((void**)&hA, g_hA);
    cudaGetSymbolAddress((void**)&hB, g_hB);
    cudaGetSymbolAddress((void**)&outb, g_out);
    cudaGetSymbolAddress((void**)&aggm, g_agg);
    cudaGetSymbolAddress((void**)&pw, g_pw);
    cudaGetSymbolAddress((void**)&counts, g_counts);
    cudaGetSymbolAddress((void**)&rowptr, g_rowptr);
    cudaGetSymbolAddress((void**)&cursor, g_cursor);
    cudaGetSymbolAddress((void**)&srcs, g_srcs);
    cudaGetSymbolAddress((void**)&bsums, g_bsums);

    const int SM_HEADS = (8192 + 8192 + 128 + 320 + 64 + 64 + 2 + 5) * 4;
    cudaFuncSetAttribute(k_sage_gemm, cudaFuncAttributeMaxDynamicSharedMemorySize, SMEM_GEMM);
    cudaFuncSetAttribute(k_att_heads, cudaFuncAttributeMaxDynamicSharedMemorySize, SM_HEADS);

    const int tiles = (n + 127) / 128;
    const int n2 = 2 * n;
    const int NB2 = (n2 + 1023) / 1024;
    const size_t COFF = (size_t)NMAX * 128;       // chain-1 offset in h buffers
    const int P2 = 2 * (E >> 1) + 2;              // vectorized edge jobs (+tail)

    // pack all weights (6 sage pairs + embedding) into fp16 [nn][k]
    k_pack<<<dim3(8, 4, 7), dim3(32, 8)>>>(Wl, Wr, w_emb, pw);

    // dual CSR build (both edge types in one pass, 2 edges/thread)
    k_count<<<(P2 + 255) / 256, 256>>>(e0, e1, counts, E, n);
    k_scan1<<<NB2, 1024>>>(counts, rowptr, bsums, n2);
    k_scan2<<<1, 256>>>(bsums, NB2, rowptr, n2);
    k_scan3<<<NB2, 1024>>>(rowptr, bsums, cursor, counts, n2);
    k_scatter<<<(P2 + 255) / 256, 256>>>(e0, e1, cursor, srcs, E, n);

    // node embedding: relu(x @ w_emb + b_emb)  (single chain, fp32 input)
    k_sage_gemm<<<tiles, 512, SMEM_GEMM>>>(nullptr, x, nullptr,
                                           pw + 6 * 32768, nullptr,
                                           b_emb, nullptr,
                                           h0, nullptr, n, tiles, 0);

    // 3 layers, both chains batched per launch
    const __half* hin0 = h0;
    const __half* hin1 = h0;
    __half* outs0[3] = { hA,        hB,        outb };
    __half* outs1[3] = { hA + COFF, hB + COFF, outb + COFF };
    for (int l = 0; l < 3; ++l) {
        const __half* pw0 = pw + (size_t)l * 32768;            // et=0, layer l
        const __half* pw1 = pw + (size_t)(3 + l) * 32768;      // et=1, layer l
        const float*  bl0 = bl + (size_t)l * 128;
        const float*  bl1 = bl + (size_t)(3 + l) * 128;
        k_gather<<<(n2 + 7) / 8, 256>>>(hin0, hin1, srcs, rowptr, aggm, n);
        k_sage_gemm<<<2 * tiles, 512, SMEM_GEMM>>>(aggm, hin0, hin1,
                                                   pw0, pw1, bl0, bl1,
                                                   outs0[l], outs1[l],
                                                   n, tiles, 1);
        hin0 = outs0[l];
        hin1 = outs1[l];
    }

    k_att_heads<<<592, 256, SM_HEADS>>>(outb, outb + COFF, w_att, b_att,
                                        w_c1, b_c1, w_c2, b_c2,
                                        w_p1, b_p1, w_p2, b_p2,
                                        (float4*)out_agg, out_fraud, out_pat, n);
}